// round 13
// baseline (speedup 1.0000x reference)
#include <cuda_runtime.h>
#include <cuda_fp16.h>

// PointWarping2 — Nadaraya-Watson Gaussian regression via tensor cores.
// S = Q~ . A~^T (mma.m16n8k8 f16, biases folded into padded K=8);
// P = ex2(S) on the f16 D-fragments (D-frag layout == next A-frag, in regs);
// (num|den) += P . G (mma, f32 accumulate).
// R13: QT=4 independent mma->ex2->mma chains per warp (latency hiding),
// MSPLIT=16, split-K + fused last-block reduction.
//
//   Q~ = (qx, qy, qz, 1, cn, 0, 0, 0),  cn = -L|q|^2
//   A~ = (2Lyx, 2Lyy, 2Lyz, aw, 1, 0, 0, 0),  aw = -L|y|^2,  L = log2e/s^2
//   G  = columns (fx, fy, fz, 1, 0, 0, 0, 0) per source
//   out = x2 - num/den   (w = 2^S is exactly the Gaussian weight)

#define Bx 2
#define N1x 8192
#define N2x 8192
#define NQ (Bx * N2x)          // 16384 queries
#define MSPLIT 16
#define TILE (N1x / MSPLIT)     // 512 sources per split
#define BLK 128
#define QT 4                    // 16-row mma tiles per warp
#define QPW (16 * QT)           // 64 queries per warp
#define QPB (QPW * 4)           // 256 queries per block
#define GRIDX (NQ / QPB)        // 64 query columns
#define FSTRIDE (TILE + 8)      // f16 elems; staggers Fc rows across banks

__device__ float4 g_partial[MSPLIT * NQ];
__device__ unsigned g_count[GRIDX];   // zero-init at load; mod trick, never reset

__device__ __forceinline__ unsigned h2ex2u(unsigned xu) {
    unsigned yu;
    asm("ex2.approx.f16x2 %0, %1;" : "=r"(yu) : "r"(xu));
    return yu;
}
__device__ __forceinline__ unsigned h22u(half2 h) {
    return *reinterpret_cast<unsigned*>(&h);
}
__device__ __forceinline__ void mma_s(unsigned& d0, unsigned& d1,
                                      unsigned a0, unsigned a1, unsigned b0) {
    unsigned z = 0u;
    asm("mma.sync.aligned.m16n8k8.row.col.f16.f16.f16.f16 "
        "{%0,%1}, {%2,%3}, {%4}, {%5,%6};"
        : "=r"(d0), "=r"(d1)
        : "r"(a0), "r"(a1), "r"(b0), "r"(z), "r"(z));
}
__device__ __forceinline__ void mma_acc(float& c0, float& c1, float& c2, float& c3,
                                        unsigned p0, unsigned p1, unsigned b0) {
    asm("mma.sync.aligned.m16n8k8.row.col.f32.f16.f16.f32 "
        "{%0,%1,%2,%3}, {%4,%5}, {%6}, {%0,%1,%2,%3};"
        : "+f"(c0), "+f"(c1), "+f"(c2), "+f"(c3)
        : "r"(p0), "r"(p1), "r"(b0));
}

// resol_factor may arrive as int32 or float32 bits; disambiguate.
__device__ __forceinline__ float read_scale(const void* p) {
    int iv = *(const int*)p;
    float f;
    if (iv > 0 && iv < 100000) f = (float)iv;
    else f = __int_as_float(iv);
    return 1.0f * f;  // INITIAL_RADIUS = 1.0
}

__global__ __launch_bounds__(BLK) void main_kernel(
    const float* __restrict__ xyz1, const float* __restrict__ xyz2,
    const float* __restrict__ flow1, const void* __restrict__ resol,
    float* __restrict__ out) {
    __shared__ uint2 sA[TILE];          // (h2(ax,ay), h2(az,aw)) per source
    __shared__ half  sFc[3 * FSTRIDE];  // component-major flow (fx|fy|fz rows)
    __shared__ unsigned s_old;

    int tid = threadIdx.x;
    int warp = tid >> 5;
    int lane = tid & 31;
    int gid = lane >> 2;     // groupID  (row / B-col selector)
    int tig = lane & 3;      // thread-in-group (K-pair selector)

    int qbase = blockIdx.x * QPB;       // block stays within one batch
    int b = qbase >> 13;

    float scale = read_scale(resol);
    float L = 1.4426950408889634f / (scale * scale);
    float t2 = 2.0f * L;

    // ---- fused prep: packed source tile ----
    const float* x1b = xyz1 + b * 3 * N1x;
    const float* f1b = flow1 + b * 3 * N1x;
    int m0 = blockIdx.y * TILE;
    #pragma unroll
    for (int i = tid; i < TILE; i += BLK) {
        int m = m0 + i;
        float fx = f1b[m], fy = f1b[N1x + m], fz = f1b[2 * N1x + m];
        float yx = x1b[m] + fx;
        float yy = x1b[N1x + m] + fy;
        float yz = x1b[2 * N1x + m] + fz;
        float aw = -L * (yx * yx + yy * yy + yz * yz);
        sA[i] = make_uint2(h22u(__floats2half2_rn(t2 * yx, t2 * yy)),
                           h22u(__floats2half2_rn(t2 * yz, aw)));
        sFc[i]               = __float2half(fx);
        sFc[FSTRIDE + i]     = __float2half(fy);
        sFc[2 * FSTRIDE + i] = __float2half(fz);
    }

    // ---- Q fragments: A-operand of mma1, per q-tile ----
    // Q~ row layout over K=8: (qx,qy | qz,1 | cn,0 | 0,0) keyed by tig.
    const float* x2b = xyz2 + b * 3 * N2x;
    int qtb = qbase + warp * QPW;
    unsigned qa0[QT], qa1[QT];
    #pragma unroll
    for (int t = 0; t < QT; t++) {
        #pragma unroll
        for (int rr = 0; rr < 2; rr++) {
            int q = qtb + t * 16 + gid + rr * 8;
            int n = q & (N2x - 1);
            float qx = x2b[n], qy = x2b[N2x + n], qz = x2b[2 * N2x + n];
            float cn = -L * (qx * qx + qy * qy + qz * qz);
            float e0, e1;
            if      (tig == 0) { e0 = qx; e1 = qy;  }
            else if (tig == 1) { e0 = qz; e1 = 1.f; }
            else if (tig == 2) { e0 = cn; e1 = 0.f; }
            else               { e0 = 0.f; e1 = 0.f; }
            unsigned v = h22u(__floats2half2_rn(e0, e1));
            if (rr == 0) qa0[t] = v; else qa1[t] = v;
        }
    }

    __syncthreads();

    // constants for the B fragments' padded lanes
    unsigned cB1 = (tig == 2) ? 0x00003C00u : 0u;   // (1.0, 0) at K=4,5
    unsigned cB2 = (gid == 3) ? 0x3C003C00u : 0u;   // G col 3 = ones
    const unsigned* aU = (const unsigned*)sA;       // [TILE*2]
    const half* fBase = sFc + gid * FSTRIDE;        // valid for gid<3

    float acc[QT][4];
    #pragma unroll
    for (int t = 0; t < QT; t++)
        acc[t][0] = acc[t][1] = acc[t][2] = acc[t][3] = 0.f;

    #pragma unroll 2
    for (int sb = 0; sb < TILE; sb += 8) {
        // mma1 B: A~^T tile — col = source (gid), K-pair selected by tig
        unsigned b1 = cB1;
        if (tig < 2) b1 = aU[2 * (sb + gid) + tig];
        // mma2 B: G tile — col = component (gid), rows = sources 2tig,2tig+1
        unsigned b2 = cB2;
        if (gid < 3) b2 = *(const unsigned*)(fBase + sb + 2 * tig);

        // 4 independent mma->ex2->mma chains: issue all S-mmas first so the
        // scheduler can overlap HMMA latency with MUFU ex2 of earlier tiles.
        unsigned s0[QT], s1[QT];
        #pragma unroll
        for (int t = 0; t < QT; t++)
            mma_s(s0[t], s1[t], qa0[t], qa1[t], b1);
        #pragma unroll
        for (int t = 0; t < QT; t++) {
            unsigned p0 = h2ex2u(s0[t]);
            unsigned p1 = h2ex2u(s1[t]);
            mma_acc(acc[t][0], acc[t][1], acc[t][2], acc[t][3], p0, p1, b2);
        }
    }

    // ---- store partials: tig 0 holds (numx,numy), tig 1 holds (numz,den) ----
    if (tig < 2) {
        #pragma unroll
        for (int t = 0; t < QT; t++) {
            int q1 = qtb + t * 16 + gid;
            int q2 = q1 + 8;
            float2* p1 = (float2*)&g_partial[blockIdx.y * NQ + q1];
            float2* p2 = (float2*)&g_partial[blockIdx.y * NQ + q2];
            p1[tig] = make_float2(acc[t][0], acc[t][1]);
            p2[tig] = make_float2(acc[t][2], acc[t][3]);
        }
    }

    // ---- last-block reduction for this query column ----
    __threadfence();
    if (tid == 0)
        s_old = atomicAdd(&g_count[blockIdx.x], 1u);
    __syncthreads();
    if ((s_old % MSPLIT) != (MSPLIT - 1)) return;

    const float* x2o = xyz2 + b * 3 * N2x;
    float* ob = out + b * 3 * N2x;
    #pragma unroll
    for (int k = 0; k < QPB / BLK; k++) {       // 2 queries per thread
        int q = qbase + tid + k * BLK;
        float rx = 0.f, ry = 0.f, rz = 0.f, rw = 0.f;
        #pragma unroll
        for (int c = 0; c < MSPLIT / 8; c++) {
            float4 v[8];
            #pragma unroll
            for (int s = 0; s < 8; s++) v[s] = g_partial[(c * 8 + s) * NQ + q];
            #pragma unroll
            for (int s = 0; s < 8; s++) {
                rx += v[s].x; ry += v[s].y; rz += v[s].z; rw += v[s].w;
            }
        }
        int n = q & (N2x - 1);
        float inv = 1.0f / rw;
        ob[0 * N2x + n] = x2o[0 * N2x + n] - rx * inv;
        ob[1 * N2x + n] = x2o[1 * N2x + n] - ry * inv;
        ob[2 * N2x + n] = x2o[2 * N2x + n] - rz * inv;
    }
}

extern "C" void kernel_launch(void* const* d_in, const int* in_sizes, int n_in,
                              void* d_out, int out_size) {
    const float* xyz1  = (const float*)d_in[0];
    const float* xyz2  = (const float*)d_in[1];
    const float* flow1 = (const float*)d_in[2];
    const void*  resol = d_in[3];
    float* out = (float*)d_out;

    dim3 grid(GRIDX, MSPLIT);   // 64 x 16 = 1024 blocks
    main_kernel<<<grid, BLK>>>(xyz1, xyz2, flow1, resol, out);
}

// round 14
// speedup vs baseline: 1.1257x; 1.1257x over previous
#include <cuda_runtime.h>
#include <cuda_fp16.h>

// PointWarping2 — Nadaraya-Watson Gaussian regression via tensor cores.
// S = Q~ . A~^T (mma.m16n8k8 f16, biases folded into padded K=8);
// P = ex2(S) on the f16 D-fragments (D-frag layout == next A-frag, in regs);
// (num|den) += P . G (mma, f32 accumulate).
// R14 = R12 inner loop (QT=2, validated 27.1us) + MSPLIT=16 -> 2048 blocks
// (~14/SM, 55 warps/SM) so tensor and MUFU pipes overlap across warps.
//
//   Q~ = (qx, qy, qz, 1, cn, 0, 0, 0),  cn = -L|q|^2
//   A~ = (2Lyx, 2Lyy, 2Lyz, aw, 1, 0, 0, 0),  aw = -L|y|^2,  L = log2e/s^2
//   G  = columns (fx, fy, fz, 1, 0, 0, 0, 0) per source
//   out = x2 - num/den   (w = 2^S is exactly the Gaussian weight)

#define Bx 2
#define N1x 8192
#define N2x 8192
#define NQ (Bx * N2x)          // 16384 queries
#define MSPLIT 16
#define TILE (N1x / MSPLIT)     // 512 sources per split
#define BLK 128
#define QT 2                    // 16-row mma tiles per warp
#define QPW (16 * QT)           // 32 queries per warp
#define QPB (QPW * 4)           // 128 queries per block
#define GRIDX (NQ / QPB)        // 128 query columns
#define FSTRIDE (TILE + 8)      // f16 elems; staggers Fc rows across banks

__device__ float4 g_partial[MSPLIT * NQ];
__device__ unsigned g_count[GRIDX];   // zero-init at load; mod trick, never reset

__device__ __forceinline__ unsigned h2ex2u(unsigned xu) {
    unsigned yu;
    asm("ex2.approx.f16x2 %0, %1;" : "=r"(yu) : "r"(xu));
    return yu;
}
__device__ __forceinline__ unsigned h22u(half2 h) {
    return *reinterpret_cast<unsigned*>(&h);
}
__device__ __forceinline__ void mma_s(unsigned& d0, unsigned& d1,
                                      unsigned a0, unsigned a1, unsigned b0) {
    unsigned z = 0u;
    asm("mma.sync.aligned.m16n8k8.row.col.f16.f16.f16.f16 "
        "{%0,%1}, {%2,%3}, {%4}, {%5,%6};"
        : "=r"(d0), "=r"(d1)
        : "r"(a0), "r"(a1), "r"(b0), "r"(z), "r"(z));
}
__device__ __forceinline__ void mma_acc(float& c0, float& c1, float& c2, float& c3,
                                        unsigned p0, unsigned p1, unsigned b0) {
    asm("mma.sync.aligned.m16n8k8.row.col.f32.f16.f16.f32 "
        "{%0,%1,%2,%3}, {%4,%5}, {%6}, {%0,%1,%2,%3};"
        : "+f"(c0), "+f"(c1), "+f"(c2), "+f"(c3)
        : "r"(p0), "r"(p1), "r"(b0));
}

// resol_factor may arrive as int32 or float32 bits; disambiguate.
__device__ __forceinline__ float read_scale(const void* p) {
    int iv = *(const int*)p;
    float f;
    if (iv > 0 && iv < 100000) f = (float)iv;
    else f = __int_as_float(iv);
    return 1.0f * f;  // INITIAL_RADIUS = 1.0
}

__global__ __launch_bounds__(BLK) void main_kernel(
    const float* __restrict__ xyz1, const float* __restrict__ xyz2,
    const float* __restrict__ flow1, const void* __restrict__ resol,
    float* __restrict__ out) {
    __shared__ uint2 sA[TILE];          // (h2(ax,ay), h2(az,aw)) per source
    __shared__ half  sFc[3 * FSTRIDE];  // component-major flow (fx|fy|fz rows)
    __shared__ unsigned s_old;

    int tid = threadIdx.x;
    int warp = tid >> 5;
    int lane = tid & 31;
    int gid = lane >> 2;     // groupID  (row / B-col selector)
    int tig = lane & 3;      // thread-in-group (K-pair selector)

    int qbase = blockIdx.x * QPB;       // block stays within one batch
    int b = qbase >> 13;

    float scale = read_scale(resol);
    float L = 1.4426950408889634f / (scale * scale);
    float t2 = 2.0f * L;

    // ---- fused prep: packed source tile ----
    const float* x1b = xyz1 + b * 3 * N1x;
    const float* f1b = flow1 + b * 3 * N1x;
    int m0 = blockIdx.y * TILE;
    #pragma unroll
    for (int i = tid; i < TILE; i += BLK) {
        int m = m0 + i;
        float fx = f1b[m], fy = f1b[N1x + m], fz = f1b[2 * N1x + m];
        float yx = x1b[m] + fx;
        float yy = x1b[N1x + m] + fy;
        float yz = x1b[2 * N1x + m] + fz;
        float aw = -L * (yx * yx + yy * yy + yz * yz);
        sA[i] = make_uint2(h22u(__floats2half2_rn(t2 * yx, t2 * yy)),
                           h22u(__floats2half2_rn(t2 * yz, aw)));
        sFc[i]               = __float2half(fx);
        sFc[FSTRIDE + i]     = __float2half(fy);
        sFc[2 * FSTRIDE + i] = __float2half(fz);
    }

    // ---- Q fragments: A-operand of mma1, per q-tile ----
    // Q~ row layout over K=8: (qx,qy | qz,1 | cn,0 | 0,0) keyed by tig.
    const float* x2b = xyz2 + b * 3 * N2x;
    int qtb = qbase + warp * QPW;
    unsigned qa0[QT], qa1[QT];
    #pragma unroll
    for (int t = 0; t < QT; t++) {
        #pragma unroll
        for (int rr = 0; rr < 2; rr++) {
            int q = qtb + t * 16 + gid + rr * 8;
            int n = q & (N2x - 1);
            float qx = x2b[n], qy = x2b[N2x + n], qz = x2b[2 * N2x + n];
            float cn = -L * (qx * qx + qy * qy + qz * qz);
            float e0, e1;
            if      (tig == 0) { e0 = qx; e1 = qy;  }
            else if (tig == 1) { e0 = qz; e1 = 1.f; }
            else if (tig == 2) { e0 = cn; e1 = 0.f; }
            else               { e0 = 0.f; e1 = 0.f; }
            unsigned v = h22u(__floats2half2_rn(e0, e1));
            if (rr == 0) qa0[t] = v; else qa1[t] = v;
        }
    }

    __syncthreads();

    // constants for the B fragments' padded lanes
    unsigned cB1 = (tig == 2) ? 0x00003C00u : 0u;   // (1.0, 0) at K=4,5
    unsigned cB2 = (gid == 3) ? 0x3C003C00u : 0u;   // G col 3 = ones
    const unsigned* aU = (const unsigned*)sA;       // [TILE*2]
    const half* fBase = sFc + gid * FSTRIDE;        // valid for gid<3

    float acc[QT][4];
    #pragma unroll
    for (int t = 0; t < QT; t++)
        acc[t][0] = acc[t][1] = acc[t][2] = acc[t][3] = 0.f;

    #pragma unroll 4
    for (int sb = 0; sb < TILE; sb += 8) {
        // mma1 B: A~^T tile — col = source (gid), K-pair selected by tig
        unsigned b1 = cB1;
        if (tig < 2) b1 = aU[2 * (sb + gid) + tig];
        // mma2 B: G tile — col = component (gid), rows = sources 2tig,2tig+1
        unsigned b2 = cB2;
        if (gid < 3) b2 = *(const unsigned*)(fBase + sb + 2 * tig);

        #pragma unroll
        for (int t = 0; t < QT; t++) {
            unsigned s0, s1;
            mma_s(s0, s1, qa0[t], qa1[t], b1);     // S = Q~ . A~^T  (f16)
            unsigned p0 = h2ex2u(s0);               // P = 2^S
            unsigned p1 = h2ex2u(s1);
            mma_acc(acc[t][0], acc[t][1], acc[t][2], acc[t][3], p0, p1, b2);
        }
    }

    // ---- store partials: tig 0 holds (numx,numy), tig 1 holds (numz,den) ----
    if (tig < 2) {
        #pragma unroll
        for (int t = 0; t < QT; t++) {
            int q1 = qtb + t * 16 + gid;
            int q2 = q1 + 8;
            float2* p1 = (float2*)&g_partial[blockIdx.y * NQ + q1];
            float2* p2 = (float2*)&g_partial[blockIdx.y * NQ + q2];
            p1[tig] = make_float2(acc[t][0], acc[t][1]);
            p2[tig] = make_float2(acc[t][2], acc[t][3]);
        }
    }

    // ---- last-block reduction for this query column ----
    __threadfence();
    if (tid == 0)
        s_old = atomicAdd(&g_count[blockIdx.x], 1u);
    __syncthreads();
    if ((s_old % MSPLIT) != (MSPLIT - 1)) return;

    {
        int q = qbase + tid;                 // 128 threads, 128 queries
        float rx = 0.f, ry = 0.f, rz = 0.f, rw = 0.f;
        #pragma unroll
        for (int c = 0; c < MSPLIT / 8; c++) {
            float4 v[8];
            #pragma unroll
            for (int s = 0; s < 8; s++) v[s] = g_partial[(c * 8 + s) * NQ + q];
            #pragma unroll
            for (int s = 0; s < 8; s++) {
                rx += v[s].x; ry += v[s].y; rz += v[s].z; rw += v[s].w;
            }
        }
        int n = q & (N2x - 1);
        float inv = 1.0f / rw;
        const float* x2o = xyz2 + b * 3 * N2x;
        float* ob = out + b * 3 * N2x;
        ob[0 * N2x + n] = x2o[0 * N2x + n] - rx * inv;
        ob[1 * N2x + n] = x2o[1 * N2x + n] - ry * inv;
        ob[2 * N2x + n] = x2o[2 * N2x + n] - rz * inv;
    }
}

extern "C" void kernel_launch(void* const* d_in, const int* in_sizes, int n_in,
                              void* d_out, int out_size) {
    const float* xyz1  = (const float*)d_in[0];
    const float* xyz2  = (const float*)d_in[1];
    const float* flow1 = (const float*)d_in[2];
    const void*  resol = d_in[3];
    float* out = (float*)d_out;

    dim3 grid(GRIDX, MSPLIT);   // 128 x 16 = 2048 blocks
    main_kernel<<<grid, BLK>>>(xyz1, xyz2, flow1, resol, out);
}

// round 15
// speedup vs baseline: 1.1482x; 1.0200x over previous
#include <cuda_runtime.h>
#include <cuda_fp16.h>

// PointWarping2 — Nadaraya-Watson Gaussian regression via tensor cores.
// S = Q~ . A~^T (mma.m16n8k8 f16, biases folded into padded K=8);
// P = ex2(S) on the f16 D-fragments (in regs);
// (num|den) += P . G via ONE mma.m16n8k16 (f32 acc) per 16 sources:
//   k16 A-frag == concat of two k8 D-frags; b0/b1 == the two G loads.
// Cuts HMMA count 8->6 per 16-source step (tensor+MUFU share a port and
// summed to ~103% of SMSP cycles in R12/R14 profiles).
//
//   Q~ = (qx, qy, qz, 1, cn, 0, 0, 0),  cn = -L|q|^2
//   A~ = (2Lyx, 2Lyy, 2Lyz, aw, 1, 0, 0, 0),  aw = -L|y|^2,  L = log2e/s^2
//   G  = columns (fx, fy, fz, 1, 0, 0, 0, 0) per source
//   out = x2 - num/den   (w = 2^S is exactly the Gaussian weight)

#define Bx 2
#define N1x 8192
#define N2x 8192
#define NQ (Bx * N2x)          // 16384 queries
#define MSPLIT 16
#define TILE (N1x / MSPLIT)     // 512 sources per split
#define BLK 128
#define QT 2                    // 16-row mma tiles per warp
#define QPW (16 * QT)           // 32 queries per warp
#define QPB (QPW * 4)           // 128 queries per block
#define GRIDX (NQ / QPB)        // 128 query columns
#define FSTRIDE (TILE + 8)      // f16 elems; staggers Fc rows across banks

__device__ float4 g_partial[MSPLIT * NQ];
__device__ unsigned g_count[GRIDX];   // zero-init at load; mod trick, never reset

__device__ __forceinline__ unsigned h2ex2u(unsigned xu) {
    unsigned yu;
    asm("ex2.approx.f16x2 %0, %1;" : "=r"(yu) : "r"(xu));
    return yu;
}
__device__ __forceinline__ unsigned h22u(half2 h) {
    return *reinterpret_cast<unsigned*>(&h);
}
__device__ __forceinline__ void mma_s(unsigned& d0, unsigned& d1,
                                      unsigned a0, unsigned a1, unsigned b0) {
    unsigned z = 0u;
    asm("mma.sync.aligned.m16n8k8.row.col.f16.f16.f16.f16 "
        "{%0,%1}, {%2,%3}, {%4}, {%5,%6};"
        : "=r"(d0), "=r"(d1)
        : "r"(a0), "r"(a1), "r"(b0), "r"(z), "r"(z));
}
// m16n8k16 f16 x f16 -> f32 accumulate: A-frag {p0a,p1a,p0b,p1b} covers
// K rows 0-7 (first k8 P tile) and 8-15 (second); B-frag {g0,g1} likewise.
__device__ __forceinline__ void mma_acc16(float& c0, float& c1, float& c2, float& c3,
                                          unsigned p0a, unsigned p1a,
                                          unsigned p0b, unsigned p1b,
                                          unsigned g0, unsigned g1) {
    asm("mma.sync.aligned.m16n8k16.row.col.f32.f16.f16.f32 "
        "{%0,%1,%2,%3}, {%4,%5,%6,%7}, {%8,%9}, {%0,%1,%2,%3};"
        : "+f"(c0), "+f"(c1), "+f"(c2), "+f"(c3)
        : "r"(p0a), "r"(p1a), "r"(p0b), "r"(p1b), "r"(g0), "r"(g1));
}

// resol_factor may arrive as int32 or float32 bits; disambiguate.
__device__ __forceinline__ float read_scale(const void* p) {
    int iv = *(const int*)p;
    float f;
    if (iv > 0 && iv < 100000) f = (float)iv;
    else f = __int_as_float(iv);
    return 1.0f * f;  // INITIAL_RADIUS = 1.0
}

__global__ __launch_bounds__(BLK) void main_kernel(
    const float* __restrict__ xyz1, const float* __restrict__ xyz2,
    const float* __restrict__ flow1, const void* __restrict__ resol,
    float* __restrict__ out) {
    __shared__ uint2 sA[TILE];          // (h2(ax,ay), h2(az,aw)) per source
    __shared__ half  sFc[3 * FSTRIDE];  // component-major flow (fx|fy|fz rows)
    __shared__ unsigned s_old;

    int tid = threadIdx.x;
    int warp = tid >> 5;
    int lane = tid & 31;
    int gid = lane >> 2;     // groupID  (row / B-col selector)
    int tig = lane & 3;      // thread-in-group (K-pair selector)

    int qbase = blockIdx.x * QPB;       // block stays within one batch
    int b = qbase >> 13;

    float scale = read_scale(resol);
    float L = 1.4426950408889634f / (scale * scale);
    float t2 = 2.0f * L;

    // ---- fused prep: packed source tile ----
    const float* x1b = xyz1 + b * 3 * N1x;
    const float* f1b = flow1 + b * 3 * N1x;
    int m0 = blockIdx.y * TILE;
    #pragma unroll
    for (int i = tid; i < TILE; i += BLK) {
        int m = m0 + i;
        float fx = f1b[m], fy = f1b[N1x + m], fz = f1b[2 * N1x + m];
        float yx = x1b[m] + fx;
        float yy = x1b[N1x + m] + fy;
        float yz = x1b[2 * N1x + m] + fz;
        float aw = -L * (yx * yx + yy * yy + yz * yz);
        sA[i] = make_uint2(h22u(__floats2half2_rn(t2 * yx, t2 * yy)),
                           h22u(__floats2half2_rn(t2 * yz, aw)));
        sFc[i]               = __float2half(fx);
        sFc[FSTRIDE + i]     = __float2half(fy);
        sFc[2 * FSTRIDE + i] = __float2half(fz);
    }

    // ---- Q fragments: A-operand of mma1, per q-tile ----
    // Q~ row layout over K=8: (qx,qy | qz,1 | cn,0 | 0,0) keyed by tig.
    const float* x2b = xyz2 + b * 3 * N2x;
    int qtb = qbase + warp * QPW;
    unsigned qa0[QT], qa1[QT];
    #pragma unroll
    for (int t = 0; t < QT; t++) {
        #pragma unroll
        for (int rr = 0; rr < 2; rr++) {
            int q = qtb + t * 16 + gid + rr * 8;
            int n = q & (N2x - 1);
            float qx = x2b[n], qy = x2b[N2x + n], qz = x2b[2 * N2x + n];
            float cn = -L * (qx * qx + qy * qy + qz * qz);
            float e0, e1;
            if      (tig == 0) { e0 = qx; e1 = qy;  }
            else if (tig == 1) { e0 = qz; e1 = 1.f; }
            else if (tig == 2) { e0 = cn; e1 = 0.f; }
            else               { e0 = 0.f; e1 = 0.f; }
            unsigned v = h22u(__floats2half2_rn(e0, e1));
            if (rr == 0) qa0[t] = v; else qa1[t] = v;
        }
    }

    __syncthreads();

    // constants for the B fragments' padded lanes
    unsigned cB1 = (tig == 2) ? 0x00003C00u : 0u;   // (1.0, 0) at K=4,5
    unsigned cB2 = (gid == 3) ? 0x3C003C00u : 0u;   // G col 3 = ones
    const unsigned* aU = (const unsigned*)sA;       // [TILE*2]
    const half* fBase = sFc + gid * FSTRIDE;        // valid for gid<3

    float acc[QT][4];
    #pragma unroll
    for (int t = 0; t < QT; t++)
        acc[t][0] = acc[t][1] = acc[t][2] = acc[t][3] = 0.f;

    #pragma unroll 4
    for (int sb = 0; sb < TILE; sb += 16) {
        // mma1 B tiles: A~^T for sources sb..sb+7 (lo) and sb+8..sb+15 (hi)
        unsigned b1lo = cB1, b1hi = cB1;
        if (tig < 2) {
            b1lo = aU[2 * (sb + gid) + tig];
            b1hi = aU[2 * (sb + 8 + gid) + tig];
        }
        // mma2 B (k16): G rows 0-7 / 8-15 for component gid
        unsigned g0 = cB2, g1 = cB2;
        if (gid < 3) {
            g0 = *(const unsigned*)(fBase + sb + 2 * tig);
            g1 = *(const unsigned*)(fBase + sb + 8 + 2 * tig);
        }

        #pragma unroll
        for (int t = 0; t < QT; t++) {
            unsigned s0a, s1a, s0b, s1b;
            mma_s(s0a, s1a, qa0[t], qa1[t], b1lo);   // S, sources 0-7
            mma_s(s0b, s1b, qa0[t], qa1[t], b1hi);   // S, sources 8-15
            unsigned p0a = h2ex2u(s0a);
            unsigned p1a = h2ex2u(s1a);
            unsigned p0b = h2ex2u(s0b);
            unsigned p1b = h2ex2u(s1b);
            mma_acc16(acc[t][0], acc[t][1], acc[t][2], acc[t][3],
                      p0a, p1a, p0b, p1b, g0, g1);
        }
    }

    // ---- store partials: tig 0 holds (numx,numy), tig 1 holds (numz,den) ----
    if (tig < 2) {
        #pragma unroll
        for (int t = 0; t < QT; t++) {
            int q1 = qtb + t * 16 + gid;
            int q2 = q1 + 8;
            float2* p1 = (float2*)&g_partial[blockIdx.y * NQ + q1];
            float2* p2 = (float2*)&g_partial[blockIdx.y * NQ + q2];
            p1[tig] = make_float2(acc[t][0], acc[t][1]);
            p2[tig] = make_float2(acc[t][2], acc[t][3]);
        }
    }

    // ---- last-block reduction for this query column ----
    __threadfence();
    if (tid == 0)
        s_old = atomicAdd(&g_count[blockIdx.x], 1u);
    __syncthreads();
    if ((s_old % MSPLIT) != (MSPLIT - 1)) return;

    {
        int q = qbase + tid;                 // 128 threads, 128 queries
        float rx = 0.f, ry = 0.f, rz = 0.f, rw = 0.f;
        #pragma unroll
        for (int c = 0; c < MSPLIT / 8; c++) {
            float4 v[8];
            #pragma unroll
            for (int s = 0; s < 8; s++) v[s] = g_partial[(c * 8 + s) * NQ + q];
            #pragma unroll
            for (int s = 0; s < 8; s++) {
                rx += v[s].x; ry += v[s].y; rz += v[s].z; rw += v[s].w;
            }
        }
        int n = q & (N2x - 1);
        float inv = 1.0f / rw;
        const float* x2o = xyz2 + b * 3 * N2x;
        float* ob = out + b * 3 * N2x;
        ob[0 * N2x + n] = x2o[0 * N2x + n] - rx * inv;
        ob[1 * N2x + n] = x2o[1 * N2x + n] - ry * inv;
        ob[2 * N2x + n] = x2o[2 * N2x + n] - rz * inv;
    }
}

extern "C" void kernel_launch(void* const* d_in, const int* in_sizes, int n_in,
                              void* d_out, int out_size) {
    const float* xyz1  = (const float*)d_in[0];
    const float* xyz2  = (const float*)d_in[1];
    const float* flow1 = (const float*)d_in[2];
    const void*  resol = d_in[3];
    float* out = (float*)d_out;

    dim3 grid(GRIDX, MSPLIT);   // 128 x 16 = 2048 blocks
    main_kernel<<<grid, BLK>>>(xyz1, xyz2, flow1, resol, out);
}